// round 7
// baseline (speedup 1.0000x reference)
#include <cuda_runtime.h>
#include <stdint.h>

#define RNODES 256
#define LUT_WORDS 8192            // 2^18 / 32
#define NSTEP 512
#define NSAMP 512
#define NIN 32
#define NOUT 10

// 6-bit half-groups: 43 (last covers k=252..255; k>=256 guarded to zero)
#define NH6 43
#define TAB6_ROWS (NH6 * 64)
// 12-bit groups: 21 full (g=0..20, k=0..251) + one 4-bit tail (k=252..255)
#define NG12 21
#define TAB12_TAIL (NG12 * 4096)        // 86016
#define TAB12_ROWS (TAB12_TAIL + 16)    // 86032 rows x 256 u16 = 44 MB

// Static device scratch (allocation-free rule).
__device__ uint32_t g_lutbits[RNODES * LUT_WORDS];   // 8 MB bit-packed LUT (L2)
__device__ uint16_t g_tab6[TAB6_ROWS * RNODES];      // 1.4 MB half tables
__device__ uint16_t g_tab12[TAB12_ROWS * RNODES];    // 44 MB combo table (L2)
__device__ uint32_t g_xpack[NSAMP * NSTEP];          // per (m,s): 32 input bits
__device__ int      g_inv[RNODES];                   // node -> input slot, or -1
__device__ int      g_init[RNODES];                  // initial state bits
__device__ int      g_mode;                          // bool enc: 0=i32 1=u8 2=f32

__device__ __forceinline__ int read_bool(const void* p, long i, int mode) {
    if (mode == 0) return ((const int*)p)[i] != 0;
    if (mode == 1) return ((const unsigned char*)p)[i] != 0;
    return ((const float*)p)[i] != 0.0f;
}

__global__ void detect_kernel(const uint32_t* __restrict__ xw) {
    int lane = threadIdx.x;
    if (blockIdx.x || lane >= 32) return;
    int isf = 0, big = 0;
    for (int i = 0; i < 32; i++) {
        uint32_t v = xw[i * 32 + lane];
        if (v == 0x3f800000u) isf = 1;
        if (v > 1u) big = 1;
    }
    unsigned af = __ballot_sync(0xffffffffu, isf);
    unsigned ab = __ballot_sync(0xffffffffu, big);
    if (lane == 0) g_mode = af ? 2 : (ab ? 1 : 0);
}

// Warp-ballot LUT pack: warp packs 32 output words from 1024 consecutive ints,
// fully coalesced 128B loads. Grid covers 2^21 words / 32 = 65536 warps.
__global__ void pack_lut_kernel(const int* __restrict__ lut) {
    int gwarp = (blockIdx.x * blockDim.x + threadIdx.x) >> 5;
    int lane  = threadIdx.x & 31;
    const int* base = lut + (size_t)gwarp * 1024;
    uint32_t mine = 0;
#pragma unroll
    for (int w = 0; w < 32; w++) {
        int v = base[w * 32 + lane];
        unsigned m = __ballot_sync(0xffffffffu, v & 1);
        if (lane == w) mine = m;
    }
    g_lutbits[(size_t)gwarp * 32 + lane] = mine;
}

// Warp-ballot x pack: 262144 words / 32 per warp = 8192 warps.
__global__ void pack_x_kernel(const void* __restrict__ x) {
    int gwarp = (blockIdx.x * blockDim.x + threadIdx.x) >> 5;
    int lane  = threadIdx.x & 31;
    int mode  = g_mode;
    long base = (long)gwarp * 1024;
    uint32_t mine = 0;
#pragma unroll
    for (int w = 0; w < 32; w++) {
        int v = read_bool(x, base + w * 32 + lane, mode);
        unsigned m = __ballot_sync(0xffffffffu, v);
        if (lane == w) mine = m;
    }
    g_xpack[gwarp * 32 + lane] = mine;
}

// misc (inv/init) + 6-bit half tables
#define SEC_MISC RNODES
#define SEC_T6   (TAB6_ROWS * RNODES)
__global__ void prep_small_kernel(const int* __restrict__ input_nodes,
                                  const void* __restrict__ init_res,
                                  const void* __restrict__ W,
                                  const int* __restrict__ primes) {
    int i = blockIdx.x * blockDim.x + threadIdx.x;
    int mode = g_mode;
    if (i < SEC_MISC) {
        int inv = -1;
#pragma unroll
        for (int q = 0; q < NIN; q++)
            if (input_nodes[q] == i) inv = q;
        g_inv[i] = inv;
        g_init[i] = read_bool(init_res, i, mode);
    }
    i -= SEC_MISC;
    if (i < 0 || i >= SEC_T6) return;
    // tab6 entry (h, c, node): sum over combo bits j of half-group h (k=6h+j)
    int node = i & 255;
    int c    = (i >> 8) & 63;
    int h    = i >> 14;
    uint32_t sum = 0;
#pragma unroll
    for (int j = 0; j < 6; j++) {
        int k = 6 * h + j;
        if ((c & (1 << j)) && k < RNODES) {
            if (read_bool(W, (long)node * RNODES + k, mode))
                sum += (uint32_t)primes[k];
        }
    }
    g_tab6[i] = (uint16_t)sum;
}

// Build 12-bit table from two 6-bit halves (write-bound, 44 MB).
__global__ void prep2_kernel() {
    int i = blockIdx.x * blockDim.x + threadIdx.x;
    if (i >= TAB12_ROWS * RNODES) return;
    int node = i & 255;
    int row  = i >> 8;
    uint16_t v;
    if (row < TAB12_TAIL) {
        int g = row >> 12;
        int c = row & 4095;
        v = (uint16_t)(g_tab6[((2 * g) * 64 + (c & 63)) * RNODES + node]
                     + g_tab6[((2 * g + 1) * 64 + (c >> 6)) * RNODES + node]);
    } else {
        int c4 = row - TAB12_TAIL;               // k = 252..255
        v = g_tab6[(42 * 64 + c4) * RNODES + node];
    }
    g_tab12[i] = v;
}

// 512 CTAs x 256 threads. CTA = one sample; thread t owns node t.
// Warp w ballots mask word w; 1 syncthreads/step (double-buffered words).
__global__ void __launch_bounds__(256, 4)
reservoir_kernel(const float* __restrict__ roW,
                 const float* __restrict__ rob,
                 float* __restrict__ out) {
    __shared__ uint32_t sh_xw[NSTEP];
    __shared__ uint32_t sh_r[16];       // 2 bufs * 8 mask words
    __shared__ float    sh_bits[RNODES];

    const int t    = threadIdx.x;       // node 0..255
    const int w    = t >> 5;
    const int lane = t & 31;
    const int sid  = blockIdx.x;

    for (int i = t; i < NSTEP; i += 256)
        sh_xw[i] = g_xpack[sid * NSTEP + i];

    const int inv = g_inv[t];
    unsigned b    = (unsigned)g_init[t];

    __syncthreads();

    for (int s = 0; s < NSTEP; s++) {
        // 1) input override (before the matvec, as in the reference)
        uint32_t xw = sh_xw[s];
        unsigned a = (inv >= 0) ? ((xw >> inv) & 1u) : b;

        // 2) state mask word w from warp w's ballot
        unsigned m = __ballot_sync(0xffffffffu, a);
        uint32_t* rb = sh_r + (s & 1) * 8;
        if (lane == 0) rb[w] = m;
        __syncthreads();

        uint4 ra  = *(const uint4*)(rb);
        uint4 rb4 = *(const uint4*)(rb + 4);
        uint32_t wv[8] = {ra.x, ra.y, ra.z, ra.w, rb4.x, rb4.y, rb4.z, rb4.w};

        // 3) 12-bit-group combo sums: 22 independent LDG.U16, plain u32 adds
        uint32_t idx = 0;
#pragma unroll
        for (int g = 0; g < NG12; g++) {
            int bp = 12 * g;
            int wi = bp >> 5, sh = bp & 31;
            uint32_t hiw = wv[(wi < 7) ? wi + 1 : 7];
            uint32_t c = __funnelshift_r(wv[wi], hiw, sh) & 0xFFFu;
            idx += (uint32_t)g_tab12[(((uint32_t)g << 12) + c) * RNODES + t];
        }
        idx += (uint32_t)g_tab12[((uint32_t)TAB12_TAIL + (wv[7] >> 28)) * RNODES + t];

        // 4) bit-packed LUT gather (8 MB, L2-resident)
        uint32_t wd = g_lutbits[((uint32_t)t << 13) + (idx >> 5)];
        b = (wd >> (idx & 31u)) & 1u;
    }

    // Readout: out[m, o] = sum_j rf[m,j] * roW[o,j] + rob[o]
    sh_bits[t] = (float)b;
    __syncthreads();

    if (t < NOUT) {
        float acc = rob[t];
        const float* wrow = roW + t * RNODES;
#pragma unroll 8
        for (int j = 0; j < RNODES; j++)
            acc += sh_bits[j] * wrow[j];
        out[sid * NOUT + t] = acc;
    }
}

extern "C" void kernel_launch(void* const* d_in, const int* in_sizes, int n_in,
                              void* d_out, int out_size) {
    const void* x       = d_in[0];                   // bool [512,512,4,8] (dtype-detected)
    const int*  innod   = (const int*)d_in[1];       // int32 [32]
    const int*  lut     = (const int*)d_in[2];       // int32 [256, 262144]
    const void* W       = d_in[3];                   // bool [256,256]
    const int*  primes  = (const int*)d_in[4];       // int32 [256]
    const void* initres = d_in[5];                   // bool [256]
    const float* roW    = (const float*)d_in[6];     // f32 [10,256]
    const float* rob    = (const float*)d_in[7];     // f32 [10]
    float* out = (float*)d_out;                      // f32 [512,10]

    detect_kernel<<<1, 32>>>((const uint32_t*)x);
    pack_lut_kernel<<<8192, 256>>>(lut);             // 65536 warps, 1 GB stream
    pack_x_kernel<<<1024, 256>>>(x);                 // 8192 warps
    prep_small_kernel<<<(SEC_MISC + SEC_T6 + 255) / 256, 256>>>(innod, initres, W, primes);
    prep2_kernel<<<(TAB12_ROWS * RNODES + 255) / 256, 256>>>();
    reservoir_kernel<<<NSAMP, 256>>>(roW, rob, out);
}

// round 8
// speedup vs baseline: 1.5278x; 1.5278x over previous
#include <cuda_runtime.h>
#include <stdint.h>

#define RNODES 256
#define LUT_WORDS 8192            // 2^18 / 32
#define NSTEP 512
#define NSAMP 512
#define NIN 32
#define NOUT 10

// 6-bit half-groups: 43 (last covers k=252..255; k>=256 guarded to zero)
#define NH6 43
#define TAB6_ROWS (NH6 * 64)
// 12-bit groups: 21 full (g=0..20, k=0..251) + one 4-bit tail (k=252..255)
#define NG12 21
#define TAB12_TAIL (NG12 * 4096)        // 86016
#define TAB12_ROWS (TAB12_TAIL + 16)    // 86032 rows x 128 u32-pairs = 44 MB

// Static device scratch (allocation-free rule).
__device__ uint32_t g_lutbits[RNODES * LUT_WORDS];   // 8 MB bit-packed LUT (L2)
__device__ uint16_t g_tab6[TAB6_ROWS * RNODES];      // 1.4 MB half tables
__device__ uint32_t g_tab12[TAB12_ROWS * 128];       // 44 MB pair table (L2)
__device__ uint32_t g_xpack[NSAMP * NSTEP];          // per (m,s): 32 input bits
__device__ int      g_inv[RNODES];                   // node -> input slot, or -1
__device__ int      g_init[RNODES];                  // initial state bits
__device__ int      g_mode;                          // bool enc: 0=i32 1=u8 2=f32

__device__ __forceinline__ int read_bool(const void* p, long i, int mode) {
    if (mode == 0) return ((const int*)p)[i] != 0;
    if (mode == 1) return ((const unsigned char*)p)[i] != 0;
    return ((const float*)p)[i] != 0.0f;
}

__global__ void detect_kernel(const uint32_t* __restrict__ xw) {
    int lane = threadIdx.x;
    if (blockIdx.x || lane >= 32) return;
    int isf = 0, big = 0;
    for (int i = 0; i < 32; i++) {
        uint32_t v = xw[i * 32 + lane];
        if (v == 0x3f800000u) isf = 1;
        if (v > 1u) big = 1;
    }
    unsigned af = __ballot_sync(0xffffffffu, isf);
    unsigned ab = __ballot_sync(0xffffffffu, big);
    if (lane == 0) g_mode = af ? 2 : (ab ? 1 : 0);
}

// Warp-ballot LUT pack: warp packs 32 output words from 1024 consecutive ints,
// fully coalesced 128B loads. 2^21 words / 32 = 65536 warps.
__global__ void pack_lut_kernel(const int* __restrict__ lut) {
    int gwarp = (blockIdx.x * blockDim.x + threadIdx.x) >> 5;
    int lane  = threadIdx.x & 31;
    const int* base = lut + (size_t)gwarp * 1024;
    uint32_t mine = 0;
#pragma unroll
    for (int w = 0; w < 32; w++) {
        int v = base[w * 32 + lane];
        unsigned m = __ballot_sync(0xffffffffu, v & 1);
        if (lane == w) mine = m;
    }
    g_lutbits[(size_t)gwarp * 32 + lane] = mine;
}

// Warp-ballot x pack: 262144 words / 32 per warp = 8192 warps.
__global__ void pack_x_kernel(const void* __restrict__ x) {
    int gwarp = (blockIdx.x * blockDim.x + threadIdx.x) >> 5;
    int lane  = threadIdx.x & 31;
    int mode  = g_mode;
    long base = (long)gwarp * 1024;
    uint32_t mine = 0;
#pragma unroll
    for (int w = 0; w < 32; w++) {
        int v = read_bool(x, base + w * 32 + lane, mode);
        unsigned m = __ballot_sync(0xffffffffu, v);
        if (lane == w) mine = m;
    }
    g_xpack[gwarp * 32 + lane] = mine;
}

// misc (inv/init) + 6-bit half tables
#define SEC_MISC RNODES
#define SEC_T6   (TAB6_ROWS * RNODES)
__global__ void prep_small_kernel(const int* __restrict__ input_nodes,
                                  const void* __restrict__ init_res,
                                  const void* __restrict__ W,
                                  const int* __restrict__ primes) {
    int i = blockIdx.x * blockDim.x + threadIdx.x;
    int mode = g_mode;
    if (i < SEC_MISC) {
        int inv = -1;
#pragma unroll
        for (int q = 0; q < NIN; q++)
            if (input_nodes[q] == i) inv = q;
        g_inv[i] = inv;
        g_init[i] = read_bool(init_res, i, mode);
    }
    i -= SEC_MISC;
    if (i < 0 || i >= SEC_T6) return;
    // tab6 entry (h, c, node): sum over combo bits j of half-group h (k=6h+j)
    int node = i & 255;
    int c    = (i >> 8) & 63;
    int h    = i >> 14;
    uint32_t sum = 0;
#pragma unroll
    for (int j = 0; j < 6; j++) {
        int k = 6 * h + j;
        if ((c & (1 << j)) && k < RNODES) {
            if (read_bool(W, (long)node * RNODES + k, mode))
                sum += (uint32_t)primes[k];
        }
    }
    g_tab6[i] = (uint16_t)sum;
}

// Build paired 12-bit table from 6-bit halves (write-bound, 44 MB).
// Entry (row, t): u16 pair {node t, node t+128}.
__global__ void prep2_kernel() {
    int i = blockIdx.x * blockDim.x + threadIdx.x;
    if (i >= TAB12_ROWS * 128) return;
    int t   = i & 127;
    int row = i >> 7;
    uint32_t lo, hi;
    if (row < TAB12_TAIL) {
        int g  = row >> 12;
        int c  = row & 4095;
        int r0 = (2 * g) * 64 + (c & 63);
        int r1 = (2 * g + 1) * 64 + (c >> 6);
        lo = (uint32_t)g_tab6[r0 * RNODES + t]
           + (uint32_t)g_tab6[r1 * RNODES + t];
        hi = (uint32_t)g_tab6[r0 * RNODES + t + 128]
           + (uint32_t)g_tab6[r1 * RNODES + t + 128];
    } else {
        int r = 42 * 64 + (row - TAB12_TAIL);     // k = 252..255
        lo = g_tab6[r * RNODES + t];
        hi = g_tab6[r * RNODES + t + 128];
    }
    g_tab12[i] = lo | (hi << 16);
}

// 512 CTAs x 128 threads. CTA = one sample; thread t owns nodes t and t+128
// (packed u16 accumulation, spilled every 3 groups). [R6 kernel, measured 461us]
__global__ void __launch_bounds__(128, 4)
reservoir_kernel(const float* __restrict__ roW,
                 const float* __restrict__ rob,
                 float* __restrict__ out) {
    __shared__ uint32_t sh_xw[NSTEP];
    __shared__ uint32_t sh_r[16];       // 2 bufs * 8 mask words
    __shared__ float    sh_bits[RNODES];

    const int t    = threadIdx.x;       // 0..127
    const int w    = t >> 5;
    const int lane = t & 31;
    const int sid  = blockIdx.x;

    for (int i = t; i < NSTEP; i += 128)
        sh_xw[i] = g_xpack[sid * NSTEP + i];

    const int inv0 = g_inv[t];
    const int inv1 = g_inv[t + 128];
    unsigned b0 = (unsigned)g_init[t];
    unsigned b1 = (unsigned)g_init[t + 128];

    __syncthreads();

    for (int s = 0; s < NSTEP; s++) {
        // 1) input override (before the matvec, as in the reference)
        uint32_t xw = sh_xw[s];
        unsigned a0 = (inv0 >= 0) ? ((xw >> inv0) & 1u) : b0;
        unsigned a1 = (inv1 >= 0) ? ((xw >> inv1) & 1u) : b1;

        // 2) state bitmask words: warp w -> words w and w+4
        unsigned m0 = __ballot_sync(0xffffffffu, a0);
        unsigned m1 = __ballot_sync(0xffffffffu, a1);
        uint32_t* rb = sh_r + (s & 1) * 8;
        if (lane == 0) { rb[w] = m0; rb[w + 4] = m1; }
        __syncthreads();

        uint4 ra  = *(const uint4*)(rb);
        uint4 rb4 = *(const uint4*)(rb + 4);
        uint32_t wv[8] = {ra.x, ra.y, ra.z, ra.w, rb4.x, rb4.y, rb4.z, rb4.w};

        // 3) 12-bit-group pair sums: 22 independent coalesced LDG.32
        uint32_t i0 = 0, i1 = 0;
#pragma unroll
        for (int trip = 0; trip < 7; trip++) {
            uint32_t acc = 0;   // packed u16; 3 groups max 3*19428 < 65536
#pragma unroll
            for (int j = 0; j < 3; j++) {
                int g  = trip * 3 + j;
                int bp = 12 * g;
                int wi = bp >> 5, sh = bp & 31;
                uint32_t c = __funnelshift_r(wv[wi], wv[(wi + 1) & 7], sh) & 0xFFFu;
                acc = __vadd2(acc, g_tab12[((uint32_t)g << 19) + (c << 7) + t]);
            }
            i0 += acc & 0xFFFFu;
            i1 += acc >> 16;
        }
        {   // tail 4-bit group (nodes k=252..255)
            uint32_t c = wv[7] >> 28;
            uint32_t e = g_tab12[((uint32_t)TAB12_TAIL << 7) + (c << 7) + t];
            i0 += e & 0xFFFFu;
            i1 += e >> 16;
        }

        // 4) bit-packed LUT gather (8 MB, L2-resident)
        uint32_t w0 = g_lutbits[((uint32_t)t << 13)         + (i0 >> 5)];
        uint32_t w1 = g_lutbits[((uint32_t)(t + 128) << 13) + (i1 >> 5)];
        b0 = (w0 >> (i0 & 31u)) & 1u;
        b1 = (w1 >> (i1 & 31u)) & 1u;
    }

    // Readout: out[m, o] = sum_j rf[m,j] * roW[o,j] + rob[o]
    sh_bits[t]       = (float)b0;
    sh_bits[t + 128] = (float)b1;
    __syncthreads();

    if (t < NOUT) {
        float acc = rob[t];
        const float* wrow = roW + t * RNODES;
#pragma unroll 8
        for (int j = 0; j < RNODES; j++)
            acc += sh_bits[j] * wrow[j];
        out[sid * NOUT + t] = acc;
    }
}

extern "C" void kernel_launch(void* const* d_in, const int* in_sizes, int n_in,
                              void* d_out, int out_size) {
    const void* x       = d_in[0];                   // bool [512,512,4,8] (dtype-detected)
    const int*  innod   = (const int*)d_in[1];       // int32 [32]
    const int*  lut     = (const int*)d_in[2];       // int32 [256, 262144]
    const void* W       = d_in[3];                   // bool [256,256]
    const int*  primes  = (const int*)d_in[4];       // int32 [256]
    const void* initres = d_in[5];                   // bool [256]
    const float* roW    = (const float*)d_in[6];     // f32 [10,256]
    const float* rob    = (const float*)d_in[7];     // f32 [10]
    float* out = (float*)d_out;                      // f32 [512,10]

    detect_kernel<<<1, 32>>>((const uint32_t*)x);
    pack_lut_kernel<<<8192, 256>>>(lut);             // 1 GB stream, DRAM-bound
    pack_x_kernel<<<1024, 256>>>(x);
    prep_small_kernel<<<(SEC_MISC + SEC_T6 + 255) / 256, 256>>>(innod, initres, W, primes);
    prep2_kernel<<<(TAB12_ROWS * 128 + 255) / 256, 256>>>();
    reservoir_kernel<<<NSAMP, 128>>>(roW, rob, out);
}